// round 5
// baseline (speedup 1.0000x reference)
#include <cuda_runtime.h>
#include <cuda_bf16.h>

// Problem constants (match reference)
#define NN   100000      // nodes
#define FIN  128         // input features
#define HID  64          // hidden
#define NCLS 40          // classes
#define NE   1600000     // edges

// Scratch (device globals — no allocation allowed)
__device__ int   g_is64;
__device__ float g_deg [NN];
__device__ float g_dinv[NN];
__device__ float g_hs1 [NN * HID];   // (x@W1)*dinv[row]
__device__ float g_acc1[NN * HID];   // hs1 + sum of neighbor hs1
__device__ float g_hs2 [NN * NCLS];  // (relu(l1)@W2)*dinv[row]

// ---------------------------------------------------------------------------
// Detect edge-index dtype at runtime (JAX may silently emit int32 even though
// the reference asks for int64). If ANY 8-byte word in the prefix is >= NN,
// the buffer cannot be int64 node indices -> it's int32.
__global__ void k_detect(const void* __restrict__ ei) {
    if (threadIdx.x == 0 && blockIdx.x == 0) {
        const unsigned long long* p = (const unsigned long long*)ei;
        int is64 = 1;
        for (int i = 0; i < 2048; i++) {
            if (p[i] >= (unsigned long long)NN) { is64 = 0; break; }
        }
        g_is64 = is64;
    }
}

__device__ __forceinline__ int edge_src(const void* __restrict__ ei, int e) {
    if (g_is64) return (int)((const long long*)ei)[e];
    return ((const int*)ei)[e];
}
__device__ __forceinline__ int edge_dst(const void* __restrict__ ei, int e) {
    if (g_is64) return (int)((const long long*)ei)[NE + e];
    return ((const int*)ei)[NE + e];
}

// ---------------------------------------------------------------------------
__global__ void k_zero_deg() {
    int i = blockIdx.x * blockDim.x + threadIdx.x;
    if (i < NN) g_deg[i] = 0.0f;
}

__global__ void k_deg(const void* __restrict__ ei) {
    int e = blockIdx.x * blockDim.x + threadIdx.x;
    if (e < NE) atomicAdd(&g_deg[edge_dst(ei, e)], 1.0f);
}

__global__ void k_dinv() {
    int i = blockIdx.x * blockDim.x + threadIdx.x;
    if (i < NN) g_dinv[i] = rsqrtf(g_deg[i] + 1.0f);
}

// ---------------------------------------------------------------------------
// GEMM1: hs1 = (x @ W1) * dinv[row];  acc1 = hs1 (self-loop init).
// One thread per row, full 64-col accumulator in registers, W1 in smem.
__global__ void k_gemm1(const float* __restrict__ x, const float* __restrict__ W1) {
    __shared__ float4 Ws[FIN * HID / 4];  // 2048 float4 = 32KB
    for (int i = threadIdx.x; i < FIN * HID / 4; i += blockDim.x)
        Ws[i] = ((const float4*)W1)[i];
    __syncthreads();

    int row = blockIdx.x * blockDim.x + threadIdx.x;
    if (row >= NN) return;

    float acc[HID];
#pragma unroll
    for (int c = 0; c < HID; c++) acc[c] = 0.0f;

    const float4* xr = (const float4*)(x + (size_t)row * FIN);
#pragma unroll 4
    for (int k4 = 0; k4 < FIN / 4; k4++) {
        float4 xv = __ldg(xr + k4);
        float xk[4] = {xv.x, xv.y, xv.z, xv.w};
#pragma unroll
        for (int kk = 0; kk < 4; kk++) {
            const float4* wr = &Ws[(k4 * 4 + kk) * (HID / 4)];
            float xs = xk[kk];
#pragma unroll
            for (int c4 = 0; c4 < HID / 4; c4++) {
                float4 w = wr[c4];
                acc[c4 * 4 + 0] += xs * w.x;
                acc[c4 * 4 + 1] += xs * w.y;
                acc[c4 * 4 + 2] += xs * w.z;
                acc[c4 * 4 + 3] += xs * w.w;
            }
        }
    }

    float di = g_dinv[row];
    float4* h1 = (float4*)(g_hs1  + (size_t)row * HID);
    float4* a1 = (float4*)(g_acc1 + (size_t)row * HID);
#pragma unroll
    for (int c4 = 0; c4 < HID / 4; c4++) {
        float4 v = make_float4(acc[c4 * 4 + 0] * di, acc[c4 * 4 + 1] * di,
                               acc[c4 * 4 + 2] * di, acc[c4 * 4 + 3] * di);
        h1[c4] = v;
        a1[c4] = v;
    }
}

// ---------------------------------------------------------------------------
// Scatter layer 1: acc1[dst] += hs1[src]  (16 float4 per edge, vector RED)
__global__ void k_scatter1(const void* __restrict__ ei) {
    int idx = blockIdx.x * blockDim.x + threadIdx.x;  // NE*16 threads
    int e = idx >> 4, g = idx & 15;
    if (e >= NE) return;
    int s = edge_src(ei, e);
    int d = edge_dst(ei, e);
    float4 v = ((const float4*)g_hs1)[s * 16 + g];
    atomicAdd(((float4*)g_acc1) + d * 16 + g, v);
}

// ---------------------------------------------------------------------------
// GEMM2: in = relu(acc1[row]*dinv[row] + b1); hs2 = (in@W2)*dinv[row];
// also initializes out = hs2 (self-loop term for layer 2).
__global__ void k_gemm2(const float* __restrict__ W2, const float* __restrict__ b1,
                        float* __restrict__ out) {
    __shared__ float4 Ws[HID * NCLS / 4];  // 640 float4 = 10KB
    __shared__ float  b1s[HID];
    for (int i = threadIdx.x; i < HID * NCLS / 4; i += blockDim.x)
        Ws[i] = ((const float4*)W2)[i];
    for (int i = threadIdx.x; i < HID; i += blockDim.x) b1s[i] = b1[i];
    __syncthreads();

    int row = blockIdx.x * blockDim.x + threadIdx.x;
    if (row >= NN) return;

    float di = g_dinv[row];
    float acc[NCLS];
#pragma unroll
    for (int c = 0; c < NCLS; c++) acc[c] = 0.0f;

    const float4* ar = (const float4*)(g_acc1 + (size_t)row * HID);
#pragma unroll 4
    for (int k4 = 0; k4 < HID / 4; k4++) {
        float4 av = ar[k4];
        float ak[4] = {av.x, av.y, av.z, av.w};
#pragma unroll
        for (int kk = 0; kk < 4; kk++) {
            int k = k4 * 4 + kk;
            float xv = fmaxf(ak[kk] * di + b1s[k], 0.0f);  // relu(l1 out)
            const float4* wr = &Ws[k * (NCLS / 4)];
#pragma unroll
            for (int c4 = 0; c4 < NCLS / 4; c4++) {
                float4 w = wr[c4];
                acc[c4 * 4 + 0] += xv * w.x;
                acc[c4 * 4 + 1] += xv * w.y;
                acc[c4 * 4 + 2] += xv * w.z;
                acc[c4 * 4 + 3] += xv * w.w;
            }
        }
    }

    float4* h2 = (float4*)(g_hs2 + (size_t)row * NCLS);
    float4* o  = (float4*)(out   + (size_t)row * NCLS);
#pragma unroll
    for (int c4 = 0; c4 < NCLS / 4; c4++) {
        float4 v = make_float4(acc[c4 * 4 + 0] * di, acc[c4 * 4 + 1] * di,
                               acc[c4 * 4 + 2] * di, acc[c4 * 4 + 3] * di);
        h2[c4] = v;
        o[c4]  = v;
    }
}

// ---------------------------------------------------------------------------
// Scatter layer 2: out[dst] += hs2[src]  (10 float4 per edge)
__global__ void k_scatter2(const void* __restrict__ ei, float* __restrict__ out) {
    int idx = blockIdx.x * blockDim.x + threadIdx.x;  // NE*10 threads
    int e = idx / 10, g = idx % 10;
    if (e >= NE) return;
    int s = edge_src(ei, e);
    int d = edge_dst(ei, e);
    float4 v = ((const float4*)g_hs2)[s * 10 + g];
    atomicAdd(((float4*)out) + d * 10 + g, v);
}

// ---------------------------------------------------------------------------
// Final: out = out * dinv[node] + b2  (in place, vectorized over float4)
__global__ void k_final(const float* __restrict__ b2, float* __restrict__ out) {
    int idx = blockIdx.x * blockDim.x + threadIdx.x;  // NN*10
    if (idx >= NN * 10) return;
    int node = idx / 10, g = idx % 10;
    float di = g_dinv[node];
    float4 bv = __ldg(((const float4*)b2) + g);
    float4* o = ((float4*)out) + idx;
    float4 v = *o;
    v.x = v.x * di + bv.x;
    v.y = v.y * di + bv.y;
    v.z = v.z * di + bv.z;
    v.w = v.w * di + bv.w;
    *o = v;
}

// ---------------------------------------------------------------------------
extern "C" void kernel_launch(void* const* d_in, const int* in_sizes, int n_in,
                              void* d_out, int out_size) {
    const float* x   = (const float*)d_in[0];
    const void*  ei  = d_in[1];                 // [2, NE], int32 OR int64
    const float* W1  = (const float*)d_in[2];
    const float* b1  = (const float*)d_in[3];
    const float* W2  = (const float*)d_in[4];
    const float* b2  = (const float*)d_in[5];
    float*       out = (float*)d_out;

    // dtype detection + degree + dinv
    k_detect<<<1, 32>>>(ei);
    k_zero_deg<<<(NN + 255) / 256, 256>>>();
    k_deg<<<(NE + 255) / 256, 256>>>(ei);
    k_dinv<<<(NN + 255) / 256, 256>>>();

    // layer 1
    k_gemm1<<<(NN + 127) / 128, 128>>>(x, W1);
    k_scatter1<<<(NE * 16) / 256, 256>>>(ei);

    // layer 2 (fuses relu(l1*dinv+b1) into GEMM2 input)
    k_gemm2<<<(NN + 127) / 128, 128>>>(W2, b1, out);
    k_scatter2<<<(NE * 10 + 319) / 320, 320>>>(ei, out);

    // epilogue: out = out*dinv + b2
    k_final<<<(NN * 10 + 255) / 256, 256>>>(b2, out);
}

// round 6
// speedup vs baseline: 1.4532x; 1.4532x over previous
#include <cuda_runtime.h>
#include <cuda_bf16.h>

// Problem constants (match reference)
#define NN   100000      // nodes
#define FIN  128         // input features
#define HID  64          // hidden
#define NCLS 40          // classes
#define NE   1600000     // edges

#define SCAN_B 1024
#define NB ((NN + SCAN_B - 1) / SCAN_B)   // 98

// Scratch (device globals — no allocation allowed)
__device__ int   g_is64;
__device__ int   g_cnt [NN];
__device__ int   g_off [NN + 1];
__device__ int   g_pos [NN];
__device__ int   g_bsum[NB];
__device__ int   g_esrc[NE];         // src indices bucketed by dst (CSR)
__device__ float g_dinv[NN];
__device__ float g_hs1 [NN * HID];   // (x@W1)*dinv[row]
__device__ float g_acc1[NN * HID];   // hs1 + sum of neighbor hs1
__device__ float g_hs2 [NN * NCLS];  // (relu(l1)@W2)*dinv[row]

// ---------------------------------------------------------------------------
// Packed f32x2 helpers (Blackwell FFMA2 — only reachable via PTX)
__device__ __forceinline__ unsigned long long pk2(float lo, float hi) {
    unsigned long long r;
    asm("mov.b64 %0, {%1, %2};" : "=l"(r) : "f"(lo), "f"(hi));
    return r;
}
__device__ __forceinline__ void fma2(unsigned long long& d,
                                     unsigned long long a, unsigned long long b) {
    asm("fma.rn.f32x2 %0, %1, %2, %0;" : "+l"(d) : "l"(a), "l"(b));
}
__device__ __forceinline__ void unpk2(unsigned long long v, float& x, float& y) {
    asm("mov.b64 {%0, %1}, %2;" : "=f"(x), "=f"(y) : "l"(v));
}

// ---------------------------------------------------------------------------
// Edge-index dtype detection (JAX silently downcasts int64 -> int32 by default)
__global__ void k_detect(const void* __restrict__ ei) {
    if (threadIdx.x == 0 && blockIdx.x == 0) {
        const unsigned long long* p = (const unsigned long long*)ei;
        int is64 = 1;
        for (int i = 0; i < 2048; i++) {
            if (p[i] >= (unsigned long long)NN) { is64 = 0; break; }
        }
        g_is64 = is64;
    }
}

__device__ __forceinline__ int edge_src(const void* __restrict__ ei, int e) {
    if (g_is64) return (int)((const long long*)ei)[e];
    return ((const int*)ei)[e];
}
__device__ __forceinline__ int edge_dst(const void* __restrict__ ei, int e) {
    if (g_is64) return (int)((const long long*)ei)[NE + e];
    return ((const int*)ei)[NE + e];
}

// ---------------------------------------------------------------------------
__global__ void k_zero_cnt() {
    int i = blockIdx.x * blockDim.x + threadIdx.x;
    if (i < NN) g_cnt[i] = 0;
}

__global__ void k_cnt(const void* __restrict__ ei) {
    int e = blockIdx.x * blockDim.x + threadIdx.x;
    if (e < NE) atomicAdd(&g_cnt[edge_dst(ei, e)], 1);
}

// Block-level inclusive scan of g_cnt; partial inclusive into g_off[i+1],
// block totals into g_bsum.
__global__ void k_scan1() {
    __shared__ int s[SCAN_B];
    int i = blockIdx.x * SCAN_B + threadIdx.x;
    s[threadIdx.x] = (i < NN) ? g_cnt[i] : 0;
    __syncthreads();
#pragma unroll
    for (int d = 1; d < SCAN_B; d <<= 1) {
        int t = (threadIdx.x >= d) ? s[threadIdx.x - d] : 0;
        __syncthreads();
        s[threadIdx.x] += t;
        __syncthreads();
    }
    if (threadIdx.x == SCAN_B - 1) g_bsum[blockIdx.x] = s[threadIdx.x];
    if (i < NN) g_off[i + 1] = s[threadIdx.x];
}

// Inclusive scan of the NB block sums (single block).
__global__ void k_scan2() {
    __shared__ int s[128];
    s[threadIdx.x] = (threadIdx.x < NB) ? g_bsum[threadIdx.x] : 0;
    __syncthreads();
#pragma unroll
    for (int d = 1; d < 128; d <<= 1) {
        int t = (threadIdx.x >= d) ? s[threadIdx.x - d] : 0;
        __syncthreads();
        s[threadIdx.x] += t;
        __syncthreads();
    }
    if (threadIdx.x < NB) g_bsum[threadIdx.x] = s[threadIdx.x];
}

// Finalize offsets, insert positions, and dinv.
__global__ void k_scan3() {
    int i = blockIdx.x * SCAN_B + threadIdx.x;
    if (i >= NN) return;
    int boff = (blockIdx.x > 0) ? g_bsum[blockIdx.x - 1] : 0;
    int cnt  = g_cnt[i];
    int incl = g_off[i + 1] + boff;
    g_off[i + 1] = incl;
    g_pos[i]     = incl - cnt;   // exclusive offset = insert cursor
    g_dinv[i]    = rsqrtf((float)cnt + 1.0f);
    if (i == 0) g_off[0] = 0;
}

// Bucket src by dst (CSR adjacency). Order within bucket is nondeterministic
// but sums are tolerance-checked.
__global__ void k_bucket(const void* __restrict__ ei) {
    int e = blockIdx.x * blockDim.x + threadIdx.x;
    if (e >= NE) return;
    int s = edge_src(ei, e);
    int d = edge_dst(ei, e);
    int p = atomicAdd(&g_pos[d], 1);
    g_esrc[p] = s;
}

// ---------------------------------------------------------------------------
// GEMM1: hs1 = (x @ W1) * dinv[row]. One thread per row, 64-col accumulator
// as 32 packed f32x2 regs, W1 in smem as ulonglong2 (direct FFMA2 operands).
__global__ void k_gemm1(const float* __restrict__ x, const float* __restrict__ W1) {
    __shared__ ulonglong2 Ws[FIN * HID / 4];  // 2048 entries = 32KB
    for (int i = threadIdx.x; i < FIN * HID / 4; i += blockDim.x)
        Ws[i] = ((const ulonglong2*)W1)[i];
    __syncthreads();

    int row = blockIdx.x * blockDim.x + threadIdx.x;
    if (row >= NN) return;

    unsigned long long acc[HID / 2];
#pragma unroll
    for (int c = 0; c < HID / 2; c++) acc[c] = 0ULL;

    const float4* xr = (const float4*)(x + (size_t)row * FIN);
#pragma unroll 2
    for (int k4 = 0; k4 < FIN / 4; k4++) {
        float4 xv = __ldg(xr + k4);
        float xk[4] = {xv.x, xv.y, xv.z, xv.w};
#pragma unroll
        for (int kk = 0; kk < 4; kk++) {
            unsigned long long xs2 = pk2(xk[kk], xk[kk]);
            const ulonglong2* wr = &Ws[(k4 * 4 + kk) * (HID / 4)];
#pragma unroll
            for (int c4 = 0; c4 < HID / 4; c4++) {
                ulonglong2 w = wr[c4];
                fma2(acc[c4 * 2 + 0], xs2, w.x);
                fma2(acc[c4 * 2 + 1], xs2, w.y);
            }
        }
    }

    float di = g_dinv[row];
    float4* h1 = (float4*)(g_hs1 + (size_t)row * HID);
#pragma unroll
    for (int c4 = 0; c4 < HID / 4; c4++) {
        float a0, a1, a2, a3;
        unpk2(acc[c4 * 2 + 0], a0, a1);
        unpk2(acc[c4 * 2 + 1], a2, a3);
        h1[c4] = make_float4(a0 * di, a1 * di, a2 * di, a3 * di);
    }
}

// ---------------------------------------------------------------------------
// Aggregation layer 1 (gather, no atomics): acc1[d] = hs1[d] + sum hs1[neigh].
// One thread per (node, float4-group), 16 groups per node.
__global__ void k_agg1() {
    int idx = blockIdx.x * blockDim.x + threadIdx.x;
    if (idx >= NN * 16) return;
    int d = idx >> 4, g = idx & 15;
    int beg = g_off[d], end = g_off[d + 1];

    const float4* h1 = (const float4*)g_hs1;
    float4 a = h1[idx];  // self-loop term (idx == d*16+g)
    int j = beg;
    for (; j + 1 < end; j += 2) {
        int s0 = __ldg(&g_esrc[j]);
        int s1 = __ldg(&g_esrc[j + 1]);
        float4 v0 = __ldg(h1 + s0 * 16 + g);
        float4 v1 = __ldg(h1 + s1 * 16 + g);
        a.x += v0.x + v1.x;
        a.y += v0.y + v1.y;
        a.z += v0.z + v1.z;
        a.w += v0.w + v1.w;
    }
    if (j < end) {
        int s0 = __ldg(&g_esrc[j]);
        float4 v0 = __ldg(h1 + s0 * 16 + g);
        a.x += v0.x; a.y += v0.y; a.z += v0.z; a.w += v0.w;
    }
    ((float4*)g_acc1)[idx] = a;
}

// ---------------------------------------------------------------------------
// GEMM2: in = relu(acc1[row]*dinv + b1); hs2 = (in @ W2) * dinv[row].
__global__ void k_gemm2(const float* __restrict__ W2, const float* __restrict__ b1) {
    __shared__ ulonglong2 Ws[HID * NCLS / 4];  // 640 entries = 10KB
    __shared__ float b1s[HID];
    for (int i = threadIdx.x; i < HID * NCLS / 4; i += blockDim.x)
        Ws[i] = ((const ulonglong2*)W2)[i];
    for (int i = threadIdx.x; i < HID; i += blockDim.x) b1s[i] = b1[i];
    __syncthreads();

    int row = blockIdx.x * blockDim.x + threadIdx.x;
    if (row >= NN) return;

    float di = g_dinv[row];
    unsigned long long acc[NCLS / 2];
#pragma unroll
    for (int c = 0; c < NCLS / 2; c++) acc[c] = 0ULL;

    const float4* ar = (const float4*)(g_acc1 + (size_t)row * HID);
#pragma unroll 2
    for (int k4 = 0; k4 < HID / 4; k4++) {
        float4 av = ar[k4];
        float ak[4] = {av.x, av.y, av.z, av.w};
#pragma unroll
        for (int kk = 0; kk < 4; kk++) {
            int k = k4 * 4 + kk;
            float xv = fmaxf(ak[kk] * di + b1s[k], 0.0f);
            unsigned long long xs2 = pk2(xv, xv);
            const ulonglong2* wr = &Ws[k * (NCLS / 4)];
#pragma unroll
            for (int c4 = 0; c4 < NCLS / 4; c4++) {
                ulonglong2 w = wr[c4];
                fma2(acc[c4 * 2 + 0], xs2, w.x);
                fma2(acc[c4 * 2 + 1], xs2, w.y);
            }
        }
    }

    float4* h2 = (float4*)(g_hs2 + (size_t)row * NCLS);
#pragma unroll
    for (int c4 = 0; c4 < NCLS / 4; c4++) {
        float a0, a1, a2, a3;
        unpk2(acc[c4 * 2 + 0], a0, a1);
        unpk2(acc[c4 * 2 + 1], a2, a3);
        h2[c4] = make_float4(a0 * di, a1 * di, a2 * di, a3 * di);
    }
}

// ---------------------------------------------------------------------------
// Aggregation layer 2 + epilogue: out[d] = (hs2[d] + sum hs2[neigh])*dinv + b2.
// One thread per (node, float4-group), 10 groups per node.
__global__ void k_agg2(const float* __restrict__ b2, float* __restrict__ out) {
    int idx = blockIdx.x * blockDim.x + threadIdx.x;
    if (idx >= NN * 10) return;
    int d = idx / 10, g = idx % 10;
    int beg = g_off[d], end = g_off[d + 1];

    const float4* h2 = (const float4*)g_hs2;
    float4 a = h2[idx];  // self-loop term
    int j = beg;
    for (; j + 1 < end; j += 2) {
        int s0 = __ldg(&g_esrc[j]);
        int s1 = __ldg(&g_esrc[j + 1]);
        float4 v0 = __ldg(h2 + s0 * 10 + g);
        float4 v1 = __ldg(h2 + s1 * 10 + g);
        a.x += v0.x + v1.x;
        a.y += v0.y + v1.y;
        a.z += v0.z + v1.z;
        a.w += v0.w + v1.w;
    }
    if (j < end) {
        int s0 = __ldg(&g_esrc[j]);
        float4 v0 = __ldg(h2 + s0 * 10 + g);
        a.x += v0.x; a.y += v0.y; a.z += v0.z; a.w += v0.w;
    }
    float di = g_dinv[d];
    float4 bv = __ldg(((const float4*)b2) + g);
    ((float4*)out)[idx] = make_float4(a.x * di + bv.x, a.y * di + bv.y,
                                      a.z * di + bv.z, a.w * di + bv.w);
}

// ---------------------------------------------------------------------------
extern "C" void kernel_launch(void* const* d_in, const int* in_sizes, int n_in,
                              void* d_out, int out_size) {
    const float* x   = (const float*)d_in[0];
    const void*  ei  = d_in[1];                 // [2, NE], int32 OR int64
    const float* W1  = (const float*)d_in[2];
    const float* b1  = (const float*)d_in[3];
    const float* W2  = (const float*)d_in[4];
    const float* b2  = (const float*)d_in[5];
    float*       out = (float*)d_out;

    // dtype detect + CSR build (count -> scan -> bucket) + dinv
    k_detect<<<1, 32>>>(ei);
    k_zero_cnt<<<(NN + 255) / 256, 256>>>();
    k_cnt<<<(NE + 255) / 256, 256>>>(ei);
    k_scan1<<<NB, SCAN_B>>>();
    k_scan2<<<1, 128>>>();
    k_scan3<<<NB, SCAN_B>>>();
    k_bucket<<<(NE + 255) / 256, 256>>>(ei);

    // layer 1
    k_gemm1<<<(NN + 127) / 128, 128>>>(x, W1);
    k_agg1<<<(NN * 16 + 255) / 256, 256>>>();

    // layer 2 (relu fused into GEMM2 input; dinv+b2 fused into agg2)
    k_gemm2<<<(NN + 127) / 128, 128>>>(W2, b1);
    k_agg2<<<(NN * 10 + 319) / 320, 320>>>(b2, out);
}

// round 7
// speedup vs baseline: 1.5877x; 1.0926x over previous
#include <cuda_runtime.h>
#include <cuda_fp16.h>
#include <cuda_bf16.h>

// Problem constants (match reference)
#define NN   100000      // nodes
#define FIN  128         // input features
#define HID  64          // hidden
#define NCLS 40          // classes
#define NE   1600000     // edges

#define SCAN_B 1024
#define NB ((NN + SCAN_B - 1) / SCAN_B)   // 98

// Scratch (device globals — no allocation allowed)
__device__ int   g_is64;
__device__ int   g_cnt [NN];
__device__ int   g_off [NN + 1];
__device__ int   g_pos [NN];
__device__ int   g_bsum[NB];
__device__ int   g_esrc[NE];          // src indices bucketed by dst (CSR)
__device__ float g_dinv[NN];
__device__ uint4 g_hs1h[NN * 8];      // (x@W1)*dinv as fp16: 64 halfs/row = 8 uint4
__device__ float g_acc1[NN * HID];    // layer-1 aggregate (fp32, linear reads)
__device__ uint4 g_hs2h[NN * 5];      // (relu@W2)*dinv as fp16: 40 halfs/row = 5 uint4

// ---------------------------------------------------------------------------
// Packed f32x2 helpers (Blackwell FFMA2 — only reachable via PTX)
__device__ __forceinline__ unsigned long long pk2(float lo, float hi) {
    unsigned long long r;
    asm("mov.b64 %0, {%1, %2};" : "=l"(r) : "f"(lo), "f"(hi));
    return r;
}
__device__ __forceinline__ void fma2(unsigned long long& d,
                                     unsigned long long a, unsigned long long b) {
    asm("fma.rn.f32x2 %0, %1, %2, %0;" : "+l"(d) : "l"(a), "l"(b));
}
__device__ __forceinline__ void unpk2(unsigned long long v, float& x, float& y) {
    asm("mov.b64 {%0, %1}, %2;" : "=f"(x), "=f"(y) : "l"(v));
}

// ---------------------------------------------------------------------------
// Edge-index dtype detection (JAX silently downcasts int64 -> int32 by default)
__global__ void k_detect(const void* __restrict__ ei) {
    if (threadIdx.x == 0 && blockIdx.x == 0) {
        const unsigned long long* p = (const unsigned long long*)ei;
        int is64 = 1;
        for (int i = 0; i < 2048; i++) {
            if (p[i] >= (unsigned long long)NN) { is64 = 0; break; }
        }
        g_is64 = is64;
    }
}

__device__ __forceinline__ int edge_src(const void* __restrict__ ei, int e) {
    if (g_is64) return (int)((const long long*)ei)[e];
    return ((const int*)ei)[e];
}
__device__ __forceinline__ int edge_dst(const void* __restrict__ ei, int e) {
    if (g_is64) return (int)((const long long*)ei)[NE + e];
    return ((const int*)ei)[NE + e];
}

// ---------------------------------------------------------------------------
__global__ void k_zero_cnt() {
    int i = blockIdx.x * blockDim.x + threadIdx.x;
    if (i < NN) g_cnt[i] = 0;
}

__global__ void k_cnt(const void* __restrict__ ei) {
    int e = blockIdx.x * blockDim.x + threadIdx.x;
    if (e < NE) atomicAdd(&g_cnt[edge_dst(ei, e)], 1);
}

// Block-level inclusive scan of g_cnt; partial inclusive into g_off[i+1],
// block totals into g_bsum.
__global__ void k_scan1() {
    __shared__ int s[SCAN_B];
    int i = blockIdx.x * SCAN_B + threadIdx.x;
    s[threadIdx.x] = (i < NN) ? g_cnt[i] : 0;
    __syncthreads();
#pragma unroll
    for (int d = 1; d < SCAN_B; d <<= 1) {
        int t = (threadIdx.x >= d) ? s[threadIdx.x - d] : 0;
        __syncthreads();
        s[threadIdx.x] += t;
        __syncthreads();
    }
    if (threadIdx.x == SCAN_B - 1) g_bsum[blockIdx.x] = s[threadIdx.x];
    if (i < NN) g_off[i + 1] = s[threadIdx.x];
}

// Inclusive scan of the NB block sums (single block).
__global__ void k_scan2() {
    __shared__ int s[128];
    s[threadIdx.x] = (threadIdx.x < NB) ? g_bsum[threadIdx.x] : 0;
    __syncthreads();
#pragma unroll
    for (int d = 1; d < 128; d <<= 1) {
        int t = (threadIdx.x >= d) ? s[threadIdx.x - d] : 0;
        __syncthreads();
        s[threadIdx.x] += t;
        __syncthreads();
    }
    if (threadIdx.x < NB) g_bsum[threadIdx.x] = s[threadIdx.x];
}

// Finalize offsets, insert positions, and dinv.
__global__ void k_scan3() {
    int i = blockIdx.x * SCAN_B + threadIdx.x;
    if (i >= NN) return;
    int boff = (blockIdx.x > 0) ? g_bsum[blockIdx.x - 1] : 0;
    int cnt  = g_cnt[i];
    int incl = g_off[i + 1] + boff;
    g_off[i + 1] = incl;
    g_pos[i]     = incl - cnt;   // exclusive offset = insert cursor
    g_dinv[i]    = rsqrtf((float)cnt + 1.0f);
    if (i == 0) g_off[0] = 0;
}

// Bucket src by dst (CSR adjacency). Order within bucket is nondeterministic
// but sums are tolerance-checked.
__global__ void k_bucket(const void* __restrict__ ei) {
    int e = blockIdx.x * blockDim.x + threadIdx.x;
    if (e >= NE) return;
    int s = edge_src(ei, e);
    int d = edge_dst(ei, e);
    int p = atomicAdd(&g_pos[d], 1);
    g_esrc[p] = s;
}

// ---------------------------------------------------------------------------
// GEMM1: hs1 = (x @ W1) * dinv[row], stored as fp16. One thread per row,
// 64-col accumulator as 32 packed f32x2 regs, W1 in smem (FFMA2 operands).
__global__ void k_gemm1(const float* __restrict__ x, const float* __restrict__ W1) {
    __shared__ ulonglong2 Ws[FIN * HID / 4];  // 2048 entries = 32KB
    for (int i = threadIdx.x; i < FIN * HID / 4; i += blockDim.x)
        Ws[i] = ((const ulonglong2*)W1)[i];
    __syncthreads();

    int row = blockIdx.x * blockDim.x + threadIdx.x;
    if (row >= NN) return;

    unsigned long long acc[HID / 2];
#pragma unroll
    for (int c = 0; c < HID / 2; c++) acc[c] = 0ULL;

    const float4* xr = (const float4*)(x + (size_t)row * FIN);
#pragma unroll 2
    for (int k4 = 0; k4 < FIN / 4; k4++) {
        float4 xv = __ldg(xr + k4);
        float xk[4] = {xv.x, xv.y, xv.z, xv.w};
#pragma unroll
        for (int kk = 0; kk < 4; kk++) {
            unsigned long long xs2 = pk2(xk[kk], xk[kk]);
            const ulonglong2* wr = &Ws[(k4 * 4 + kk) * (HID / 4)];
#pragma unroll
            for (int c4 = 0; c4 < HID / 4; c4++) {
                ulonglong2 w = wr[c4];
                fma2(acc[c4 * 2 + 0], xs2, w.x);
                fma2(acc[c4 * 2 + 1], xs2, w.y);
            }
        }
    }

    float di = g_dinv[row];
    uint4* h1 = &g_hs1h[row * 8];
#pragma unroll
    for (int j = 0; j < 8; j++) {   // uint4 j covers cols 8j..8j+7 = acc[4j..4j+3]
        uint4 v;
        unsigned int* vp = (unsigned int*)&v;
#pragma unroll
        for (int q = 0; q < 4; q++) {
            float lo, hi;
            unpk2(acc[4 * j + q], lo, hi);
            __half2 h = __floats2half2_rn(lo * di, hi * di);
            vp[q] = *(unsigned int*)&h;
        }
        h1[j] = v;
    }
}

// ---------------------------------------------------------------------------
// Aggregation layer 1 (gather, no atomics): acc1[d] = hs1[d] + sum hs1[neigh].
// One thread per (node, 8-half group), 8 groups per node. fp32 accumulate.
__global__ void k_agg1() {
    int idx = blockIdx.x * blockDim.x + threadIdx.x;
    if (idx >= NN * 8) return;
    int d = idx >> 3, g = idx & 7;
    int beg = g_off[d], end = g_off[d + 1];

    float a[8];
    {
        uint4 v = g_hs1h[idx];  // self-loop term (idx == d*8+g)
        const __half2* hp = (const __half2*)&v;
#pragma unroll
        for (int q = 0; q < 4; q++) {
            float2 f = __half22float2(hp[q]);
            a[2 * q] = f.x; a[2 * q + 1] = f.y;
        }
    }
    for (int j = beg; j < end; j++) {
        int s = __ldg(&g_esrc[j]);
        uint4 v = __ldg(&g_hs1h[s * 8 + g]);
        const __half2* hp = (const __half2*)&v;
#pragma unroll
        for (int q = 0; q < 4; q++) {
            float2 f = __half22float2(hp[q]);
            a[2 * q] += f.x; a[2 * q + 1] += f.y;
        }
    }
    float4* o = (float4*)(g_acc1 + (size_t)d * HID + g * 8);
    o[0] = make_float4(a[0], a[1], a[2], a[3]);
    o[1] = make_float4(a[4], a[5], a[6], a[7]);
}

// ---------------------------------------------------------------------------
// GEMM2: in = relu(acc1[row]*dinv + b1); hs2 = (in @ W2) * dinv[row] as fp16.
__global__ void k_gemm2(const float* __restrict__ W2, const float* __restrict__ b1) {
    __shared__ ulonglong2 Ws[HID * NCLS / 4];  // 640 entries = 10KB
    __shared__ float b1s[HID];
    for (int i = threadIdx.x; i < HID * NCLS / 4; i += blockDim.x)
        Ws[i] = ((const ulonglong2*)W2)[i];
    for (int i = threadIdx.x; i < HID; i += blockDim.x) b1s[i] = b1[i];
    __syncthreads();

    int row = blockIdx.x * blockDim.x + threadIdx.x;
    if (row >= NN) return;

    float di = g_dinv[row];
    unsigned long long acc[NCLS / 2];
#pragma unroll
    for (int c = 0; c < NCLS / 2; c++) acc[c] = 0ULL;

    const float4* ar = (const float4*)(g_acc1 + (size_t)row * HID);
#pragma unroll 2
    for (int k4 = 0; k4 < HID / 4; k4++) {
        float4 av = ar[k4];
        float ak[4] = {av.x, av.y, av.z, av.w};
#pragma unroll
        for (int kk = 0; kk < 4; kk++) {
            int k = k4 * 4 + kk;
            float xv = fmaxf(ak[kk] * di + b1s[k], 0.0f);
            unsigned long long xs2 = pk2(xv, xv);
            const ulonglong2* wr = &Ws[k * (NCLS / 4)];
#pragma unroll
            for (int c4 = 0; c4 < NCLS / 4; c4++) {
                ulonglong2 w = wr[c4];
                fma2(acc[c4 * 2 + 0], xs2, w.x);
                fma2(acc[c4 * 2 + 1], xs2, w.y);
            }
        }
    }

    uint4* h2 = &g_hs2h[row * 5];
#pragma unroll
    for (int j = 0; j < 5; j++) {   // uint4 j covers cols 8j..8j+7 = acc[4j..4j+3]
        uint4 v;
        unsigned int* vp = (unsigned int*)&v;
#pragma unroll
        for (int q = 0; q < 4; q++) {
            float lo, hi;
            unpk2(acc[4 * j + q], lo, hi);
            __half2 h = __floats2half2_rn(lo * di, hi * di);
            vp[q] = *(unsigned int*)&h;
        }
        h2[j] = v;
    }
}

// ---------------------------------------------------------------------------
// Aggregation layer 2 + epilogue: out[d] = (hs2[d] + sum hs2[neigh])*dinv + b2.
// One thread per (node, 8-half group), 5 groups per node.
__global__ void k_agg2(const float* __restrict__ b2, float* __restrict__ out) {
    int idx = blockIdx.x * blockDim.x + threadIdx.x;
    if (idx >= NN * 5) return;
    int d = idx / 5, g = idx - d * 5;
    int beg = g_off[d], end = g_off[d + 1];

    float a[8];
    {
        uint4 v = g_hs2h[idx];  // self-loop term (idx == d*5+g)
        const __half2* hp = (const __half2*)&v;
#pragma unroll
        for (int q = 0; q < 4; q++) {
            float2 f = __half22float2(hp[q]);
            a[2 * q] = f.x; a[2 * q + 1] = f.y;
        }
    }
    for (int j = beg; j < end; j++) {
        int s = __ldg(&g_esrc[j]);
        uint4 v = __ldg(&g_hs2h[s * 5 + g]);
        const __half2* hp = (const __half2*)&v;
#pragma unroll
        for (int q = 0; q < 4; q++) {
            float2 f = __half22float2(hp[q]);
            a[2 * q] += f.x; a[2 * q + 1] += f.y;
        }
    }
    float di = g_dinv[d];
    const float4* bp = (const float4*)(b2 + g * 8);
    float4 b0 = __ldg(bp), b1v = __ldg(bp + 1);
    float4* o = (float4*)(out + (size_t)d * NCLS + g * 8);
    o[0] = make_float4(a[0] * di + b0.x, a[1] * di + b0.y,
                       a[2] * di + b0.z, a[3] * di + b0.w);
    o[1] = make_float4(a[4] * di + b1v.x, a[5] * di + b1v.y,
                       a[6] * di + b1v.z, a[7] * di + b1v.w);
}

// ---------------------------------------------------------------------------
extern "C" void kernel_launch(void* const* d_in, const int* in_sizes, int n_in,
                              void* d_out, int out_size) {
    const float* x   = (const float*)d_in[0];
    const void*  ei  = d_in[1];                 // [2, NE], int32 OR int64
    const float* W1  = (const float*)d_in[2];
    const float* b1  = (const float*)d_in[3];
    const float* W2  = (const float*)d_in[4];
    const float* b2  = (const float*)d_in[5];
    float*       out = (float*)d_out;

    // dtype detect + CSR build (count -> scan -> bucket) + dinv
    k_detect<<<1, 32>>>(ei);
    k_zero_cnt<<<(NN + 255) / 256, 256>>>();
    k_cnt<<<(NE + 255) / 256, 256>>>(ei);
    k_scan1<<<NB, SCAN_B>>>();
    k_scan2<<<1, 128>>>();
    k_scan3<<<NB, SCAN_B>>>();
    k_bucket<<<(NE + 255) / 256, 256>>>(ei);

    // layer 1
    k_gemm1<<<(NN + 127) / 128, 128>>>(x, W1);
    k_agg1<<<(NN * 8 + 255) / 256, 256>>>();

    // layer 2 (relu fused into GEMM2 input; dinv+b2 fused into agg2)
    k_gemm2<<<(NN + 127) / 128, 128>>>(W2, b1);
    k_agg2<<<(NN * 5 + 319) / 320, 320>>>(b2, out);
}

// round 8
// speedup vs baseline: 1.6717x; 1.0529x over previous
#include <cuda_runtime.h>
#include <cuda_fp16.h>
#include <cuda_bf16.h>

// Problem constants (match reference)
#define NN   100000      // nodes
#define FIN  128         // input features
#define HID  64          // hidden
#define NCLS 40          // classes
#define NE   1600000     // edges

#define SCAN_B 1024
#define NB ((NN + SCAN_B - 1) / SCAN_B)   // 98
#define GEMM1_BLOCKS ((NN + 127) / 128)   // 782
#define CNT_BLOCKS 1024

// Scratch (device globals — no allocation allowed)
__device__ int   g_is64;
__device__ int   g_cnt [NN];
__device__ int   g_off [NN + 1];
__device__ int   g_pos [NN];
__device__ int   g_bsum[NB];
__device__ int   g_esrc[NE];          // src indices bucketed by dst (CSR)
__device__ float g_dinv[NN];
__device__ uint4 g_hs1h[NN * 8];      // x@W1 (UNSCALED) fp16: 64 halfs/row
__device__ float g_acc1[NN * HID];    // layer-1 aggregate (fp32, linear reads)
__device__ uint4 g_hs2h[NN * 5];      // (relu@W2)*dinv fp16: 40 halfs/row

// ---------------------------------------------------------------------------
// Packed f32x2 helpers (Blackwell FFMA2 — only reachable via PTX)
__device__ __forceinline__ unsigned long long pk2(float lo, float hi) {
    unsigned long long r;
    asm("mov.b64 %0, {%1, %2};" : "=l"(r) : "f"(lo), "f"(hi));
    return r;
}
__device__ __forceinline__ void fma2(unsigned long long& d,
                                     unsigned long long a, unsigned long long b) {
    asm("fma.rn.f32x2 %0, %1, %2, %0;" : "+l"(d) : "l"(a), "l"(b));
}
__device__ __forceinline__ void unpk2(unsigned long long v, float& x, float& y) {
    asm("mov.b64 {%0, %1}, %2;" : "=f"(x), "=f"(y) : "l"(v));
}

// ---------------------------------------------------------------------------
// Edge-index dtype detection (JAX silently downcasts int64 -> int32 by default)
__device__ __forceinline__ int edge_src(const void* __restrict__ ei, int e) {
    if (g_is64) return (int)((const long long*)ei)[e];
    return ((const int*)ei)[e];
}
__device__ __forceinline__ int edge_dst(const void* __restrict__ ei, int e) {
    if (g_is64) return (int)((const long long*)ei)[NE + e];
    return ((const int*)ei)[NE + e];
}

// Fused: detect dtype (block 0, thread 0) + zero g_cnt (all threads)
__global__ void k_init(const void* __restrict__ ei) {
    if (blockIdx.x == 0 && threadIdx.x == 0) {
        const unsigned long long* p = (const unsigned long long*)ei;
        int is64 = 1;
        for (int i = 0; i < 2048; i++) {
            if (p[i] >= (unsigned long long)NN) { is64 = 0; break; }
        }
        g_is64 = is64;
    }
    int i = blockIdx.x * blockDim.x + threadIdx.x;
    if (i < NN) g_cnt[i] = 0;
}

// ---------------------------------------------------------------------------
// FUSED: GEMM1 (blocks [0, GEMM1_BLOCKS)) + degree count (remaining blocks).
// GEMM1: hs1 = x @ W1 (UNSCALED), stored fp16. dinv applied later in agg1,
// which removes the scan3 -> gemm1 dependency and lets the FMA-bound GEMM
// overlap the memory/atomic-bound count pass in one launch.
__global__ void k_gemm1_cnt(const float* __restrict__ x,
                            const float* __restrict__ W1,
                            const void* __restrict__ ei) {
    __shared__ ulonglong2 Ws[FIN * HID / 4];  // 2048 entries = 32KB

    if (blockIdx.x >= GEMM1_BLOCKS) {
        // --- degree count role ---
        int t = (blockIdx.x - GEMM1_BLOCKS) * blockDim.x + threadIdx.x;
        int stride = CNT_BLOCKS * blockDim.x;
        for (int e = t; e < NE; e += stride)
            atomicAdd(&g_cnt[edge_dst(ei, e)], 1);
        return;
    }

    // --- GEMM role ---
    for (int i = threadIdx.x; i < FIN * HID / 4; i += blockDim.x)
        Ws[i] = ((const ulonglong2*)W1)[i];
    __syncthreads();

    int row = blockIdx.x * blockDim.x + threadIdx.x;
    if (row >= NN) return;

    unsigned long long acc[HID / 2];
#pragma unroll
    for (int c = 0; c < HID / 2; c++) acc[c] = 0ULL;

    const float4* xr = (const float4*)(x + (size_t)row * FIN);
#pragma unroll 2
    for (int k4 = 0; k4 < FIN / 4; k4++) {
        float4 xv = __ldg(xr + k4);
        float xk[4] = {xv.x, xv.y, xv.z, xv.w};
#pragma unroll
        for (int kk = 0; kk < 4; kk++) {
            unsigned long long xs2 = pk2(xk[kk], xk[kk]);
            const ulonglong2* wr = &Ws[(k4 * 4 + kk) * (HID / 4)];
#pragma unroll
            for (int c4 = 0; c4 < HID / 4; c4++) {
                ulonglong2 w = wr[c4];
                fma2(acc[c4 * 2 + 0], xs2, w.x);
                fma2(acc[c4 * 2 + 1], xs2, w.y);
            }
        }
    }

    uint4* h1 = &g_hs1h[row * 8];
#pragma unroll
    for (int j = 0; j < 8; j++) {
        uint4 v;
        unsigned int* vp = (unsigned int*)&v;
#pragma unroll
        for (int q = 0; q < 4; q++) {
            float lo, hi;
            unpk2(acc[4 * j + q], lo, hi);
            __half2 h = __floats2half2_rn(lo, hi);
            vp[q] = *(unsigned int*)&h;
        }
        h1[j] = v;
    }
}

// ---------------------------------------------------------------------------
// Scan 1: warp-shuffle block scan of g_cnt -> partial inclusive in g_off[i+1],
// block totals in g_bsum.
__global__ void k_scan1() {
    __shared__ int wsum[32];
    int i = blockIdx.x * SCAN_B + threadIdx.x;
    int lane = threadIdx.x & 31, wid = threadIdx.x >> 5;
    int s = (i < NN) ? g_cnt[i] : 0;
#pragma unroll
    for (int d = 1; d < 32; d <<= 1) {
        int t = __shfl_up_sync(0xFFFFFFFFu, s, d);
        if (lane >= d) s += t;
    }
    if (lane == 31) wsum[wid] = s;
    __syncthreads();
    if (wid == 0) {
        int w = wsum[lane];
#pragma unroll
        for (int d = 1; d < 32; d <<= 1) {
            int t = __shfl_up_sync(0xFFFFFFFFu, w, d);
            if (lane >= d) w += t;
        }
        wsum[lane] = w;
    }
    __syncthreads();
    if (wid > 0) s += wsum[wid - 1];
    if (threadIdx.x == SCAN_B - 1) g_bsum[blockIdx.x] = s;
    if (i < NN) g_off[i + 1] = s;
}

// Scan 2: inclusive scan of NB block sums (single block, shuffle-based).
__global__ void k_scan2() {
    __shared__ int wsum[4];
    int lane = threadIdx.x & 31, wid = threadIdx.x >> 5;
    int s = (threadIdx.x < NB) ? g_bsum[threadIdx.x] : 0;
#pragma unroll
    for (int d = 1; d < 32; d <<= 1) {
        int t = __shfl_up_sync(0xFFFFFFFFu, s, d);
        if (lane >= d) s += t;
    }
    if (lane == 31) wsum[wid] = s;
    __syncthreads();
    if (threadIdx.x == 0) {
        int acc = 0;
#pragma unroll
        for (int w = 0; w < 4; w++) { int t = wsum[w]; wsum[w] = acc; acc += t; }
    }
    __syncthreads();
    s += wsum[wid];
    if (threadIdx.x < NB) g_bsum[threadIdx.x] = s;
}

// Scan 3: finalize offsets, insert cursors, dinv.
__global__ void k_scan3() {
    int i = blockIdx.x * SCAN_B + threadIdx.x;
    if (i >= NN) return;
    int boff = (blockIdx.x > 0) ? g_bsum[blockIdx.x - 1] : 0;
    int cnt  = g_cnt[i];
    int incl = g_off[i + 1] + boff;
    g_off[i + 1] = incl;
    g_pos[i]     = incl - cnt;
    g_dinv[i]    = rsqrtf((float)cnt + 1.0f);
    if (i == 0) g_off[0] = 0;
}

// Bucket src by dst (CSR adjacency).
__global__ void k_bucket(const void* __restrict__ ei) {
    int e = blockIdx.x * blockDim.x + threadIdx.x;
    if (e >= NE) return;
    int s = edge_src(ei, e);
    int d = edge_dst(ei, e);
    int p = atomicAdd(&g_pos[d], 1);
    g_esrc[p] = s;
}

// ---------------------------------------------------------------------------
// Aggregation layer 1: acc1[d] = dinv[d]*h1[d] + sum_s dinv[s]*h1[s].
// One thread per (node, 8-half group); fp32 accumulate.
__global__ void k_agg1() {
    int idx = blockIdx.x * blockDim.x + threadIdx.x;
    if (idx >= NN * 8) return;
    int d = idx >> 3, g = idx & 7;
    int beg = g_off[d], end = g_off[d + 1];

    float a[8];
    {
        float dd = g_dinv[d];
        uint4 v = g_hs1h[idx];  // self term (idx == d*8+g)
        const __half2* hp = (const __half2*)&v;
#pragma unroll
        for (int q = 0; q < 4; q++) {
            float2 f = __half22float2(hp[q]);
            a[2 * q] = dd * f.x; a[2 * q + 1] = dd * f.y;
        }
    }
    for (int j = beg; j < end; j++) {
        int s = __ldg(&g_esrc[j]);
        float ds = __ldg(&g_dinv[s]);
        uint4 v = __ldg(&g_hs1h[s * 8 + g]);
        const __half2* hp = (const __half2*)&v;
#pragma unroll
        for (int q = 0; q < 4; q++) {
            float2 f = __half22float2(hp[q]);
            a[2 * q]     = fmaf(ds, f.x, a[2 * q]);
            a[2 * q + 1] = fmaf(ds, f.y, a[2 * q + 1]);
        }
    }
    float4* o = (float4*)(g_acc1 + (size_t)d * HID + g * 8);
    o[0] = make_float4(a[0], a[1], a[2], a[3]);
    o[1] = make_float4(a[4], a[5], a[6], a[7]);
}

// ---------------------------------------------------------------------------
// GEMM2: in = relu(acc1[row]*dinv + b1); hs2 = (in @ W2) * dinv[row] as fp16.
__global__ void k_gemm2(const float* __restrict__ W2, const float* __restrict__ b1) {
    __shared__ ulonglong2 Ws[HID * NCLS / 4];  // 640 entries = 10KB
    __shared__ float b1s[HID];
    for (int i = threadIdx.x; i < HID * NCLS / 4; i += blockDim.x)
        Ws[i] = ((const ulonglong2*)W2)[i];
    for (int i = threadIdx.x; i < HID; i += blockDim.x) b1s[i] = b1[i];
    __syncthreads();

    int row = blockIdx.x * blockDim.x + threadIdx.x;
    if (row >= NN) return;

    float di = g_dinv[row];
    unsigned long long acc[NCLS / 2];
#pragma unroll
    for (int c = 0; c < NCLS / 2; c++) acc[c] = 0ULL;

    const float4* ar = (const float4*)(g_acc1 + (size_t)row * HID);
#pragma unroll 2
    for (int k4 = 0; k4 < HID / 4; k4++) {
        float4 av = ar[k4];
        float ak[4] = {av.x, av.y, av.z, av.w};
#pragma unroll
        for (int kk = 0; kk < 4; kk++) {
            int k = k4 * 4 + kk;
            float xv = fmaxf(ak[kk] * di + b1s[k], 0.0f);
            unsigned long long xs2 = pk2(xv, xv);
            const ulonglong2* wr = &Ws[k * (NCLS / 4)];
#pragma unroll
            for (int c4 = 0; c4 < NCLS / 4; c4++) {
                ulonglong2 w = wr[c4];
                fma2(acc[c4 * 2 + 0], xs2, w.x);
                fma2(acc[c4 * 2 + 1], xs2, w.y);
            }
        }
    }

    uint4* h2 = &g_hs2h[row * 5];
#pragma unroll
    for (int j = 0; j < 5; j++) {
        uint4 v;
        unsigned int* vp = (unsigned int*)&v;
#pragma unroll
        for (int q = 0; q < 4; q++) {
            float lo, hi;
            unpk2(acc[4 * j + q], lo, hi);
            __half2 h = __floats2half2_rn(lo * di, hi * di);
            vp[q] = *(unsigned int*)&h;
        }
        h2[j] = v;
    }
}

// ---------------------------------------------------------------------------
// Aggregation layer 2 + epilogue: out[d] = (hs2[d] + sum hs2[neigh])*dinv + b2.
__global__ void k_agg2(const float* __restrict__ b2, float* __restrict__ out) {
    int idx = blockIdx.x * blockDim.x + threadIdx.x;
    if (idx >= NN * 5) return;
    int d = idx / 5, g = idx - d * 5;
    int beg = g_off[d], end = g_off[d + 1];

    float a[8];
    {
        uint4 v = g_hs2h[idx];  // self term (idx == d*5+g)
        const __half2* hp = (const __half2*)&v;
#pragma unroll
        for (int q = 0; q < 4; q++) {
            float2 f = __half22float2(hp[q]);
            a[2 * q] = f.x; a[2 * q + 1] = f.y;
        }
    }
    for (int j = beg; j < end; j++) {
        int s = __ldg(&g_esrc[j]);
        uint4 v = __ldg(&g_hs2h[s * 5 + g]);
        const __half2* hp = (const __half2*)&v;
#pragma unroll
        for (int q = 0; q < 4; q++) {
            float2 f = __half22float2(hp[q]);
            a[2 * q] += f.x; a[2 * q + 1] += f.y;
        }
    }
    float di = g_dinv[d];
    const float4* bp = (const float4*)(b2 + g * 8);
    float4 b0 = __ldg(bp), b1v = __ldg(bp + 1);
    float4* o = (float4*)(out + (size_t)d * NCLS + g * 8);
    o[0] = make_float4(a[0] * di + b0.x, a[1] * di + b0.y,
                       a[2] * di + b0.z, a[3] * di + b0.w);
    o[1] = make_float4(a[4] * di + b1v.x, a[5] * di + b1v.y,
                       a[6] * di + b1v.z, a[7] * di + b1v.w);
}

// ---------------------------------------------------------------------------
extern "C" void kernel_launch(void* const* d_in, const int* in_sizes, int n_in,
                              void* d_out, int out_size) {
    const float* x   = (const float*)d_in[0];
    const void*  ei  = d_in[1];                 // [2, NE], int32 OR int64
    const float* W1  = (const float*)d_in[2];
    const float* b1  = (const float*)d_in[3];
    const float* W2  = (const float*)d_in[4];
    const float* b2  = (const float*)d_in[5];
    float*       out = (float*)d_out;

    // init (dtype detect + zero counts)
    k_init<<<(NN + 255) / 256, 256>>>(ei);

    // GEMM1 (unscaled) overlapped with degree count in one launch
    k_gemm1_cnt<<<GEMM1_BLOCKS + CNT_BLOCKS, 128>>>(x, W1, ei);

    // CSR build: scan + bucket (+ dinv in scan3)
    k_scan1<<<NB, SCAN_B>>>();
    k_scan2<<<1, 128>>>();
    k_scan3<<<NB, SCAN_B>>>();
    k_bucket<<<(NE + 255) / 256, 256>>>(ei);

    // layer 1 aggregate (applies dinv[s] / dinv[d])
    k_agg1<<<(NN * 8 + 255) / 256, 256>>>();

    // layer 2 (relu fused into GEMM2 input; dinv+b2 fused into agg2)
    k_gemm2<<<(NN + 127) / 128, 128>>>(W2, b1);
    k_agg2<<<(NN * 5 + 319) / 320, 320>>>(b2, out);
}